// round 1
// baseline (speedup 1.0000x reference)
#include <cuda_runtime.h>
#include <math.h>

// Problem constants
// B=16, N=M=512, VS=2048, QS=1024, OS=2048, H=16, DH=128
// v_trans/q_trans: [8192, 6144]; updates: [8192, 2048]
#define ROWS      8192        // B * 512
#define TRANS_W   6144        // 3 * OS
#define OS_W      2048

// -------------------- scratch (device globals; no allocations allowed) -----
__device__ float g_vtrans[(size_t)ROWS * TRANS_W];
__device__ float g_qtrans[(size_t)ROWS * TRANS_W];
__device__ float g_vupd  [(size_t)ROWS * OS_W];
__device__ float g_qupd  [(size_t)ROWS * OS_W];

// ============================================================================
// SGEMM: C[M,N] (+)= A[M,K] @ B[K,N], optional epilogue relu(x+bias)*mask[row]
// Tiles: 128x128x8, 256 threads, 8x8 per-thread register tile.
// Requires: M%128==0, N%128==0, K%8==0 (true for all shapes here).
// ============================================================================
__global__ void __launch_bounds__(256)
sgemm_kernel(const float* __restrict__ A, const float* __restrict__ Bm,
             float* __restrict__ C,
             const float* __restrict__ bias, const float* __restrict__ mask,
             int M, int N, int K, int accumulate, int epilogue)
{
    __shared__ float As[8][128];   // transposed A tile: As[k][m]
    __shared__ float Bs[8][128];

    const int tid  = threadIdx.x;
    const int trow = tid >> 4;          // 0..15 -> rows trow*8..+8
    const int tcol = tid & 15;          // 0..15 -> cols tcol*8..+8

    const int aRow = tid >> 1;          // 0..127
    const int aCol = (tid & 1) << 2;    // 0 or 4
    const int bRow = tid >> 5;          // 0..7
    const int bCol = (tid & 31) << 2;   // 0..124

    const float* Ap = A  + (size_t)(blockIdx.y * 128 + aRow) * K + aCol;
    const float* Bp = Bm + (size_t)bRow * N + blockIdx.x * 128 + bCol;

    float acc[8][8];
#pragma unroll
    for (int i = 0; i < 8; i++)
#pragma unroll
        for (int j = 0; j < 8; j++) acc[i][j] = 0.0f;

    for (int k0 = 0; k0 < K; k0 += 8) {
        float4 a4 = *(const float4*)Ap;
        float4 b4 = *(const float4*)Bp;
        As[aCol + 0][aRow] = a4.x;
        As[aCol + 1][aRow] = a4.y;
        As[aCol + 2][aRow] = a4.z;
        As[aCol + 3][aRow] = a4.w;
        *(float4*)&Bs[bRow][bCol] = b4;
        __syncthreads();
        Ap += 8;
        Bp += (size_t)8 * N;

#pragma unroll
        for (int k = 0; k < 8; k++) {
            float ra[8], rb[8];
            *(float4*)&ra[0] = *(const float4*)&As[k][trow * 8];
            *(float4*)&ra[4] = *(const float4*)&As[k][trow * 8 + 4];
            *(float4*)&rb[0] = *(const float4*)&Bs[k][tcol * 8];
            *(float4*)&rb[4] = *(const float4*)&Bs[k][tcol * 8 + 4];
#pragma unroll
            for (int i = 0; i < 8; i++)
#pragma unroll
                for (int j = 0; j < 8; j++)
                    acc[i][j] += ra[i] * rb[j];
        }
        __syncthreads();
    }

    const int crow0 = blockIdx.y * 128 + trow * 8;
    const int ccol0 = blockIdx.x * 128 + tcol * 8;
#pragma unroll
    for (int i = 0; i < 8; i++) {
        float* cp = C + (size_t)(crow0 + i) * N + ccol0;
        const float mrow = mask ? mask[crow0 + i] : 1.0f;
#pragma unroll
        for (int j4 = 0; j4 < 8; j4 += 4) {
            float4 v;
            v.x = acc[i][j4 + 0];
            v.y = acc[i][j4 + 1];
            v.z = acc[i][j4 + 2];
            v.w = acc[i][j4 + 3];
            if (accumulate) {
                float4 o = *(const float4*)(cp + j4);
                v.x += o.x; v.y += o.y; v.z += o.z; v.w += o.w;
            }
            if (epilogue) {
                v.x = fmaxf(v.x + bias[ccol0 + j4 + 0], 0.0f) * mrow;
                v.y = fmaxf(v.y + bias[ccol0 + j4 + 1], 0.0f) * mrow;
                v.z = fmaxf(v.z + bias[ccol0 + j4 + 2], 0.0f) * mrow;
                v.w = fmaxf(v.w + bias[ccol0 + j4 + 3], 0.0f) * mrow;
            }
            *(float4*)(cp + j4) = v;
        }
    }
}

// ============================================================================
// Fused attention (flash-style, fp32).
//   out[b, nq, h*128 + d] = softmax_m( Q[b,nq,h]·K[b,m,h] * scale  (masked) ) @ V
// Q slice from Tq at col offset 2048 + h*128 (qry), K at h*128 (key),
// V at 4096 + h*128 (val). Tq/Tk row stride = 6144. Lq = Lk = 512.
// Block: 256 threads, 64 query rows; 8 key tiles of 64.
// Thread (sr=tid/16, sc=tid%15): score tile rows sr*4..+4, cols sc*4..+4;
// PV tile rows sr*4..+4, cols sc*8..+8.
// ============================================================================
struct AttnSmem {
    float Qs[64][129];
    float Ks[64][129];
    float Vs[64][128];
    float Ss[64][65];
    float Mk[64];
};

__global__ void __launch_bounds__(256)
attn_kernel(const float* __restrict__ Tq, const float* __restrict__ Tk,
            const float* __restrict__ maskK, float* __restrict__ out)
{
    extern __shared__ char smem_raw[];
    AttnSmem& sm = *reinterpret_cast<AttnSmem*>(smem_raw);

    const int b  = blockIdx.z;
    const int h  = blockIdx.y;
    const int qt = blockIdx.x;
    const int tid = threadIdx.x;
    const int sr = tid >> 4;   // 0..15
    const int sc = tid & 15;   // 0..15
    const float SCALE = 0.08838834764831845f;  // 1/sqrt(128)

    // Load Q tile [64 x 128]
    const float* qbase = Tq + ((size_t)(b * 512 + qt * 64)) * 6144 + 2048 + h * 128;
#pragma unroll
    for (int c = 0; c < 8; c++) {
        int lin = c * 256 + tid;
        int r = lin >> 5;
        int c4 = (lin & 31) << 2;
        float4 v = *(const float4*)(qbase + (size_t)r * 6144 + c4);
        sm.Qs[r][c4 + 0] = v.x;
        sm.Qs[r][c4 + 1] = v.y;
        sm.Qs[r][c4 + 2] = v.z;
        sm.Qs[r][c4 + 3] = v.w;
    }

    float m_i[4], l_i[4], acc[4][8];
#pragma unroll
    for (int ii = 0; ii < 4; ii++) {
        m_i[ii] = -INFINITY;
        l_i[ii] = 0.0f;
#pragma unroll
        for (int j = 0; j < 8; j++) acc[ii][j] = 0.0f;
    }

    const float* kbase = Tk + (size_t)b * 512 * 6144 + h * 128;      // keys
    const float* vbase = kbase + 4096;                                // vals

    for (int kt = 0; kt < 8; kt++) {
        __syncthreads();  // protect Ks/Vs/Ss WAR across warps
        const float* kp = kbase + (size_t)(kt * 64) * 6144;
        const float* vp = vbase + (size_t)(kt * 64) * 6144;
#pragma unroll
        for (int c = 0; c < 8; c++) {
            int lin = c * 256 + tid;
            int r = lin >> 5;
            int c4 = (lin & 31) << 2;
            float4 kv = *(const float4*)(kp + (size_t)r * 6144 + c4);
            sm.Ks[r][c4 + 0] = kv.x;
            sm.Ks[r][c4 + 1] = kv.y;
            sm.Ks[r][c4 + 2] = kv.z;
            sm.Ks[r][c4 + 3] = kv.w;
            float4 vv = *(const float4*)(vp + (size_t)r * 6144 + c4);
            *(float4*)&sm.Vs[r][c4] = vv;
        }
        if (tid < 64) sm.Mk[tid] = maskK[b * 512 + kt * 64 + tid];
        __syncthreads();

        // ---- scores: 4x4 per thread over dh=128 ----
        float s[4][4];
#pragma unroll
        for (int ii = 0; ii < 4; ii++)
#pragma unroll
            for (int jj = 0; jj < 4; jj++) s[ii][jj] = 0.0f;

#pragma unroll 8
        for (int k = 0; k < 128; k++) {
            float q0 = sm.Qs[sr * 4 + 0][k];
            float q1 = sm.Qs[sr * 4 + 1][k];
            float q2 = sm.Qs[sr * 4 + 2][k];
            float q3 = sm.Qs[sr * 4 + 3][k];
#pragma unroll
            for (int jj = 0; jj < 4; jj++) {
                float kv = sm.Ks[sc * 4 + jj][k];
                s[0][jj] += q0 * kv;
                s[1][jj] += q1 * kv;
                s[2][jj] += q2 * kv;
                s[3][jj] += q3 * kv;
            }
        }

        // mask + scale
        float keep[4];
#pragma unroll
        for (int jj = 0; jj < 4; jj++) keep[jj] = sm.Mk[sc * 4 + jj];
#pragma unroll
        for (int ii = 0; ii < 4; ii++)
#pragma unroll
            for (int jj = 0; jj < 4; jj++)
                s[ii][jj] = (keep[jj] != 0.0f) ? s[ii][jj] * SCALE : -INFINITY;

        // online softmax update (per row, reduce over 16 lanes of the row group)
#pragma unroll
        for (int ii = 0; ii < 4; ii++) {
            float tmax = fmaxf(fmaxf(s[ii][0], s[ii][1]), fmaxf(s[ii][2], s[ii][3]));
            tmax = fmaxf(tmax, __shfl_xor_sync(0xffffffffu, tmax, 1));
            tmax = fmaxf(tmax, __shfl_xor_sync(0xffffffffu, tmax, 2));
            tmax = fmaxf(tmax, __shfl_xor_sync(0xffffffffu, tmax, 4));
            tmax = fmaxf(tmax, __shfl_xor_sync(0xffffffffu, tmax, 8));
            float mnew  = fmaxf(m_i[ii], tmax);
            float msafe = (mnew == -INFINITY) ? 0.0f : mnew;
            float corr  = __expf(m_i[ii] - msafe);   // m_i=-inf -> 0
            float lsum = 0.0f;
#pragma unroll
            for (int jj = 0; jj < 4; jj++) {
                float p = __expf(s[ii][jj] - msafe);
                sm.Ss[sr * 4 + ii][sc * 4 + jj] = p;
                lsum += p;
            }
            lsum += __shfl_xor_sync(0xffffffffu, lsum, 1);
            lsum += __shfl_xor_sync(0xffffffffu, lsum, 2);
            lsum += __shfl_xor_sync(0xffffffffu, lsum, 4);
            lsum += __shfl_xor_sync(0xffffffffu, lsum, 8);
            l_i[ii] = l_i[ii] * corr + lsum;
            m_i[ii] = mnew;
#pragma unroll
            for (int j = 0; j < 8; j++) acc[ii][j] *= corr;
        }
        __syncwarp();  // Ss written/read within the same warp's row group

        // ---- PV: rows sr*4..+4, output cols sc*8..+8 ----
#pragma unroll 4
        for (int m = 0; m < 64; m++) {
            float4 v0 = *(const float4*)&sm.Vs[m][sc * 8];
            float4 v1 = *(const float4*)&sm.Vs[m][sc * 8 + 4];
#pragma unroll
            for (int ii = 0; ii < 4; ii++) {
                float p = sm.Ss[sr * 4 + ii][m];
                acc[ii][0] += p * v0.x;
                acc[ii][1] += p * v0.y;
                acc[ii][2] += p * v0.z;
                acc[ii][3] += p * v0.w;
                acc[ii][4] += p * v1.x;
                acc[ii][5] += p * v1.y;
                acc[ii][6] += p * v1.z;
                acc[ii][7] += p * v1.w;
            }
        }
    }

    // write output
#pragma unroll
    for (int ii = 0; ii < 4; ii++) {
        float inv = (l_i[ii] > 0.0f) ? (1.0f / l_i[ii]) : 0.0f;
        size_t orow = (size_t)(b * 512 + qt * 64 + sr * 4 + ii);
        float* op = out + orow * 2048 + h * 128 + sc * 8;
        float4 o0, o1;
        o0.x = acc[ii][0] * inv; o0.y = acc[ii][1] * inv;
        o0.z = acc[ii][2] * inv; o0.w = acc[ii][3] * inv;
        o1.x = acc[ii][4] * inv; o1.y = acc[ii][5] * inv;
        o1.z = acc[ii][6] * inv; o1.w = acc[ii][7] * inv;
        *(float4*)op       = o0;
        *(float4*)(op + 4) = o1;
    }
}

// ============================================================================
extern "C" void kernel_launch(void* const* d_in, const int* in_sizes, int n_in,
                              void* d_out, int out_size)
{
    (void)in_sizes; (void)n_in; (void)out_size;
    const float* v     = (const float*)d_in[0];
    const float* q     = (const float*)d_in[1];
    const float* vmask = (const float*)d_in[2];
    const float* qmask = (const float*)d_in[3];
    const float* Wv    = (const float*)d_in[4];
    const float* bv    = (const float*)d_in[5];
    const float* Wq    = (const float*)d_in[6];
    const float* bq    = (const float*)d_in[7];
    const float* Wvo   = (const float*)d_in[8];
    const float* bvo   = (const float*)d_in[9];
    const float* Wqo   = (const float*)d_in[10];
    const float* bqo   = (const float*)d_in[11];

    float* out_v = (float*)d_out;                         // [8192, 2048]
    float* out_q = out_v + (size_t)ROWS * OS_W;           // [8192, 2048]

    float *vtrans, *qtrans, *vupd, *qupd;
    cudaGetSymbolAddress((void**)&vtrans, g_vtrans);
    cudaGetSymbolAddress((void**)&qtrans, g_qtrans);
    cudaGetSymbolAddress((void**)&vupd,   g_vupd);
    cudaGetSymbolAddress((void**)&qupd,   g_qupd);

    cudaFuncSetAttribute(attn_kernel, cudaFuncAttributeMaxDynamicSharedMemorySize,
                         (int)sizeof(AttnSmem));

    dim3 blk(256);

    // 1) v_trans = relu(v @ Wv + bv) * v_mask     [8192,6144] K=2048
    sgemm_kernel<<<dim3(TRANS_W / 128, ROWS / 128), blk>>>(
        v, Wv, vtrans, bv, vmask, ROWS, TRANS_W, 2048, 0, 1);
    // 2) q_trans = relu(q @ Wq + bq) * q_mask     [8192,6144] K=1024
    sgemm_kernel<<<dim3(TRANS_W / 128, ROWS / 128), blk>>>(
        q, Wq, qtrans, bq, qmask, ROWS, TRANS_W, 1024, 0, 1);

    // 3) q2v attention: queries=v_trans, keys/vals=q_trans, mask=q_mask -> v_update
    attn_kernel<<<dim3(8, 16, 16), blk, sizeof(AttnSmem)>>>(vtrans, qtrans, qmask, vupd);
    // 4) v2q attention: queries=q_trans, keys/vals=v_trans, mask=v_mask -> q_update
    attn_kernel<<<dim3(8, 16, 16), blk, sizeof(AttnSmem)>>>(qtrans, vtrans, vmask, qupd);

    // 5) updated_v = relu([v, v_update] @ Wvo + bvo)   (split-K accumulate)
    sgemm_kernel<<<dim3(OS_W / 128, ROWS / 128), blk>>>(
        v, Wvo, out_v, nullptr, nullptr, ROWS, OS_W, 2048, 0, 0);
    sgemm_kernel<<<dim3(OS_W / 128, ROWS / 128), blk>>>(
        vupd, Wvo + (size_t)2048 * OS_W, out_v, bvo, nullptr, ROWS, OS_W, 2048, 1, 1);

    // 6) updated_q = relu([q, q_update] @ Wqo + bqo)
    sgemm_kernel<<<dim3(OS_W / 128, ROWS / 128), blk>>>(
        q, Wqo, out_q, nullptr, nullptr, ROWS, OS_W, 1024, 0, 0);
    sgemm_kernel<<<dim3(OS_W / 128, ROWS / 128), blk>>>(
        qupd, Wqo + (size_t)1024 * OS_W, out_q, bqo, nullptr, ROWS, OS_W, 2048, 1, 1);
}

// round 2
// speedup vs baseline: 2.4193x; 2.4193x over previous
#include <cuda_runtime.h>
#include <math.h>

// Problem constants
// B=16, N=M=512, VS=2048, QS=1024, OS=2048, H=16, DH=128
#define ROWS      8192        // B * 512
#define TRANS_W   6144        // 3 * OS
#define OS_W      2048

// -------------------- scratch (device globals; no allocations allowed) -----
__device__ float g_vtrans[(size_t)ROWS * TRANS_W];
__device__ float g_qtrans[(size_t)ROWS * TRANS_W];
__device__ float g_vupd  [(size_t)ROWS * OS_W];
__device__ float g_qupd  [(size_t)ROWS * OS_W];

// ============================================================================
// TF32 tensor-core GEMM: C[M,N] (+)= A[M,K] @ B[K,N]
// epilogue: relu(x + bias[col]) * mask[row]  (optional)
// CTA tile 128x128, BK=16, 256 threads = 8 warps (2x4), warp tile 64x32.
// mma.sync.aligned.m16n8k8 tf32. Requires M%128==0, N%128==0, K%16==0.
// ============================================================================
#define BM 128
#define BN 128
#define BK 16
#define AS_STRIDE 20    // conflict-free for a-frag scalar loads
#define BS_STRIDE 136   // conflict-free for b-frag scalar loads

__device__ __forceinline__ unsigned f2tf32(float x) {
    unsigned r;
    asm("cvt.rna.tf32.f32 %0, %1;" : "=r"(r) : "f"(x));
    return r;
}

__device__ __forceinline__ void mma_tf32(float c[4], const unsigned a[4], const unsigned b[2]) {
    asm volatile(
        "mma.sync.aligned.m16n8k8.row.col.f32.tf32.tf32.f32 "
        "{%0,%1,%2,%3}, {%4,%5,%6,%7}, {%8,%9}, {%0,%1,%2,%3};\n"
        : "+f"(c[0]), "+f"(c[1]), "+f"(c[2]), "+f"(c[3])
        : "r"(a[0]), "r"(a[1]), "r"(a[2]), "r"(a[3]),
          "r"(b[0]), "r"(b[1]));
}

__global__ void __launch_bounds__(256, 2)
mma_gemm_kernel(const float* __restrict__ A, const float* __restrict__ Bm,
                float* __restrict__ C,
                const float* __restrict__ bias, const float* __restrict__ mask,
                int M, int N, int K, int accumulate, int epilogue)
{
    __shared__ unsigned As[BM][AS_STRIDE];   // [m][k], tf32 bits
    __shared__ unsigned Bs[BK][BS_STRIDE];   // [k][n], tf32 bits

    const int tid  = threadIdx.x;
    const int lane = tid & 31;
    const int warp = tid >> 5;
    const int wm = (warp >> 2) * 64;   // 0 or 64
    const int wn = (warp & 3) * 32;    // 0,32,64,96

    const int rowBase = blockIdx.y * BM;
    const int colBase = blockIdx.x * BN;

    // ---- gmem load indexing (float4 granularity) ----
    // A tile: 128 rows x 16 cols = 512 float4; thread handles f = tid, tid+256
    // B tile:  16 rows x 128 cols = 512 float4
    const int aR0 = tid >> 2;              // f=tid:    row 0..63
    const int aK0 = (tid & 3) << 2;        // k offset 0/4/8/12
    const int aR1 = (tid + 256) >> 2;      // row 64..127
    const int bR0 = tid >> 5;              // k row 0..7
    const int bC0 = (tid & 31) << 2;       // col 0..124
    const int bR1 = (tid + 256) >> 5;      // k row 8..15

    const float* Ap0 = A + (size_t)(rowBase + aR0) * K + aK0;
    const float* Ap1 = A + (size_t)(rowBase + aR1) * K + aK0;
    const float* Bp0 = Bm + (size_t)bR0 * N + colBase + bC0;
    const float* Bp1 = Bm + (size_t)bR1 * N + colBase + bC0;

    float acc[4][4][4];
#pragma unroll
    for (int i = 0; i < 4; i++)
#pragma unroll
        for (int j = 0; j < 4; j++)
#pragma unroll
            for (int r = 0; r < 4; r++) acc[i][j][r] = 0.0f;

    const int kChunks = K / BK;

    float4 ra0 = *(const float4*)Ap0;
    float4 ra1 = *(const float4*)Ap1;
    float4 rb0 = *(const float4*)Bp0;
    float4 rb1 = *(const float4*)Bp1;

    for (int ck = 0; ck < kChunks; ck++) {
        // store prefetched regs -> smem (convert to tf32)
        As[aR0][aK0 + 0] = f2tf32(ra0.x);
        As[aR0][aK0 + 1] = f2tf32(ra0.y);
        As[aR0][aK0 + 2] = f2tf32(ra0.z);
        As[aR0][aK0 + 3] = f2tf32(ra0.w);
        As[aR1][aK0 + 0] = f2tf32(ra1.x);
        As[aR1][aK0 + 1] = f2tf32(ra1.y);
        As[aR1][aK0 + 2] = f2tf32(ra1.z);
        As[aR1][aK0 + 3] = f2tf32(ra1.w);
        Bs[bR0][bC0 + 0] = f2tf32(rb0.x);
        Bs[bR0][bC0 + 1] = f2tf32(rb0.y);
        Bs[bR0][bC0 + 2] = f2tf32(rb0.z);
        Bs[bR0][bC0 + 3] = f2tf32(rb0.w);
        Bs[bR1][bC0 + 0] = f2tf32(rb1.x);
        Bs[bR1][bC0 + 1] = f2tf32(rb1.y);
        Bs[bR1][bC0 + 2] = f2tf32(rb1.z);
        Bs[bR1][bC0 + 3] = f2tf32(rb1.w);
        __syncthreads();

        if (ck + 1 < kChunks) {
            Ap0 += BK; Ap1 += BK;
            Bp0 += (size_t)BK * N; Bp1 += (size_t)BK * N;
            ra0 = *(const float4*)Ap0;
            ra1 = *(const float4*)Ap1;
            rb0 = *(const float4*)Bp0;
            rb1 = *(const float4*)Bp1;
        }

        // compute: two k8 steps
#pragma unroll
        for (int ks = 0; ks < 2; ks++) {
            const int k0 = ks * 8;
            unsigned afr[4][4];
#pragma unroll
            for (int mt = 0; mt < 4; mt++) {
                int r = wm + mt * 16 + (lane >> 2);
                int kk = k0 + (lane & 3);
                afr[mt][0] = As[r][kk];
                afr[mt][1] = As[r + 8][kk];
                afr[mt][2] = As[r][kk + 4];
                afr[mt][3] = As[r + 8][kk + 4];
            }
            unsigned bfr[4][2];
#pragma unroll
            for (int nt = 0; nt < 4; nt++) {
                int c = wn + nt * 8 + (lane >> 2);
                int kk = k0 + (lane & 3);
                bfr[nt][0] = Bs[kk][c];
                bfr[nt][1] = Bs[kk + 4][c];
            }
#pragma unroll
            for (int mt = 0; mt < 4; mt++)
#pragma unroll
                for (int nt = 0; nt < 4; nt++)
                    mma_tf32(acc[mt][nt], afr[mt], bfr[nt]);
        }
        __syncthreads();
    }

    // ---- epilogue ----
#pragma unroll
    for (int mt = 0; mt < 4; mt++) {
        const int r0 = rowBase + wm + mt * 16 + (lane >> 2);
        const int r1 = r0 + 8;
        const float m0 = mask ? mask[r0] : 1.0f;
        const float m1 = mask ? mask[r1] : 1.0f;
#pragma unroll
        for (int nt = 0; nt < 4; nt++) {
            const int c = colBase + wn + nt * 8 + ((lane & 3) << 1);
            float2 v0, v1;
            v0.x = acc[mt][nt][0]; v0.y = acc[mt][nt][1];
            v1.x = acc[mt][nt][2]; v1.y = acc[mt][nt][3];
            float* p0 = C + (size_t)r0 * N + c;
            float* p1 = C + (size_t)r1 * N + c;
            if (accumulate) {
                float2 o0 = *(const float2*)p0;
                float2 o1 = *(const float2*)p1;
                v0.x += o0.x; v0.y += o0.y;
                v1.x += o1.x; v1.y += o1.y;
            }
            if (epilogue) {
                float b0 = bias[c], b1 = bias[c + 1];
                v0.x = fmaxf(v0.x + b0, 0.0f) * m0;
                v0.y = fmaxf(v0.y + b1, 0.0f) * m0;
                v1.x = fmaxf(v1.x + b0, 0.0f) * m1;
                v1.y = fmaxf(v1.y + b1, 0.0f) * m1;
            }
            *(float2*)p0 = v0;
            *(float2*)p1 = v1;
        }
    }
}

// ============================================================================
// Fused attention (flash-style, fp32) — unchanged from R1 (passing).
// ============================================================================
struct AttnSmem {
    float Qs[64][129];
    float Ks[64][129];
    float Vs[64][128];
    float Ss[64][65];
    float Mk[64];
};

__global__ void __launch_bounds__(256)
attn_kernel(const float* __restrict__ Tq, const float* __restrict__ Tk,
            const float* __restrict__ maskK, float* __restrict__ out)
{
    extern __shared__ char smem_raw[];
    AttnSmem& sm = *reinterpret_cast<AttnSmem*>(smem_raw);

    const int b  = blockIdx.z;
    const int h  = blockIdx.y;
    const int qt = blockIdx.x;
    const int tid = threadIdx.x;
    const int sr = tid >> 4;
    const int sc = tid & 15;
    const float SCALE = 0.08838834764831845f;  // 1/sqrt(128)

    const float* qbase = Tq + ((size_t)(b * 512 + qt * 64)) * 6144 + 2048 + h * 128;
#pragma unroll
    for (int c = 0; c < 8; c++) {
        int lin = c * 256 + tid;
        int r = lin >> 5;
        int c4 = (lin & 31) << 2;
        float4 v = *(const float4*)(qbase + (size_t)r * 6144 + c4);
        sm.Qs[r][c4 + 0] = v.x;
        sm.Qs[r][c4 + 1] = v.y;
        sm.Qs[r][c4 + 2] = v.z;
        sm.Qs[r][c4 + 3] = v.w;
    }

    float m_i[4], l_i[4], acc[4][8];
#pragma unroll
    for (int ii = 0; ii < 4; ii++) {
        m_i[ii] = -INFINITY;
        l_i[ii] = 0.0f;
#pragma unroll
        for (int j = 0; j < 8; j++) acc[ii][j] = 0.0f;
    }

    const float* kbase = Tk + (size_t)b * 512 * 6144 + h * 128;
    const float* vbase = kbase + 4096;

    for (int kt = 0; kt < 8; kt++) {
        __syncthreads();
        const float* kp = kbase + (size_t)(kt * 64) * 6144;
        const float* vp = vbase + (size_t)(kt * 64) * 6144;
#pragma unroll
        for (int c = 0; c < 8; c++) {
            int lin = c * 256 + tid;
            int r = lin >> 5;
            int c4 = (lin & 31) << 2;
            float4 kv = *(const float4*)(kp + (size_t)r * 6144 + c4);
            sm.Ks[r][c4 + 0] = kv.x;
            sm.Ks[r][c4 + 1] = kv.y;
            sm.Ks[r][c4 + 2] = kv.z;
            sm.Ks[r][c4 + 3] = kv.w;
            float4 vv = *(const float4*)(vp + (size_t)r * 6144 + c4);
            *(float4*)&sm.Vs[r][c4] = vv;
        }
        if (tid < 64) sm.Mk[tid] = maskK[b * 512 + kt * 64 + tid];
        __syncthreads();

        float s[4][4];
#pragma unroll
        for (int ii = 0; ii < 4; ii++)
#pragma unroll
            for (int jj = 0; jj < 4; jj++) s[ii][jj] = 0.0f;

#pragma unroll 8
        for (int k = 0; k < 128; k++) {
            float q0 = sm.Qs[sr * 4 + 0][k];
            float q1 = sm.Qs[sr * 4 + 1][k];
            float q2 = sm.Qs[sr * 4 + 2][k];
            float q3 = sm.Qs[sr * 4 + 3][k];
#pragma unroll
            for (int jj = 0; jj < 4; jj++) {
                float kv = sm.Ks[sc * 4 + jj][k];
                s[0][jj] += q0 * kv;
                s[1][jj] += q1 * kv;
                s[2][jj] += q2 * kv;
                s[3][jj] += q3 * kv;
            }
        }

        float keep[4];
#pragma unroll
        for (int jj = 0; jj < 4; jj++) keep[jj] = sm.Mk[sc * 4 + jj];
#pragma unroll
        for (int ii = 0; ii < 4; ii++)
#pragma unroll
            for (int jj = 0; jj < 4; jj++)
                s[ii][jj] = (keep[jj] != 0.0f) ? s[ii][jj] * SCALE : -INFINITY;

#pragma unroll
        for (int ii = 0; ii < 4; ii++) {
            float tmax = fmaxf(fmaxf(s[ii][0], s[ii][1]), fmaxf(s[ii][2], s[ii][3]));
            tmax = fmaxf(tmax, __shfl_xor_sync(0xffffffffu, tmax, 1));
            tmax = fmaxf(tmax, __shfl_xor_sync(0xffffffffu, tmax, 2));
            tmax = fmaxf(tmax, __shfl_xor_sync(0xffffffffu, tmax, 4));
            tmax = fmaxf(tmax, __shfl_xor_sync(0xffffffffu, tmax, 8));
            float mnew  = fmaxf(m_i[ii], tmax);
            float msafe = (mnew == -INFINITY) ? 0.0f : mnew;
            float corr  = __expf(m_i[ii] - msafe);
            float lsum = 0.0f;
#pragma unroll
            for (int jj = 0; jj < 4; jj++) {
                float p = __expf(s[ii][jj] - msafe);
                sm.Ss[sr * 4 + ii][sc * 4 + jj] = p;
                lsum += p;
            }
            lsum += __shfl_xor_sync(0xffffffffu, lsum, 1);
            lsum += __shfl_xor_sync(0xffffffffu, lsum, 2);
            lsum += __shfl_xor_sync(0xffffffffu, lsum, 4);
            lsum += __shfl_xor_sync(0xffffffffu, lsum, 8);
            l_i[ii] = l_i[ii] * corr + lsum;
            m_i[ii] = mnew;
#pragma unroll
            for (int j = 0; j < 8; j++) acc[ii][j] *= corr;
        }
        __syncwarp();

#pragma unroll 4
        for (int m = 0; m < 64; m++) {
            float4 v0 = *(const float4*)&sm.Vs[m][sc * 8];
            float4 v1 = *(const float4*)&sm.Vs[m][sc * 8 + 4];
#pragma unroll
            for (int ii = 0; ii < 4; ii++) {
                float p = sm.Ss[sr * 4 + ii][m];
                acc[ii][0] += p * v0.x;
                acc[ii][1] += p * v0.y;
                acc[ii][2] += p * v0.z;
                acc[ii][3] += p * v0.w;
                acc[ii][4] += p * v1.x;
                acc[ii][5] += p * v1.y;
                acc[ii][6] += p * v1.z;
                acc[ii][7] += p * v1.w;
            }
        }
    }

#pragma unroll
    for (int ii = 0; ii < 4; ii++) {
        float inv = (l_i[ii] > 0.0f) ? (1.0f / l_i[ii]) : 0.0f;
        size_t orow = (size_t)(b * 512 + qt * 64 + sr * 4 + ii);
        float* op = out + orow * 2048 + h * 128 + sc * 8;
        float4 o0, o1;
        o0.x = acc[ii][0] * inv; o0.y = acc[ii][1] * inv;
        o0.z = acc[ii][2] * inv; o0.w = acc[ii][3] * inv;
        o1.x = acc[ii][4] * inv; o1.y = acc[ii][5] * inv;
        o1.z = acc[ii][6] * inv; o1.w = acc[ii][7] * inv;
        *(float4*)op       = o0;
        *(float4*)(op + 4) = o1;
    }
}

// ============================================================================
extern "C" void kernel_launch(void* const* d_in, const int* in_sizes, int n_in,
                              void* d_out, int out_size)
{
    (void)in_sizes; (void)n_in; (void)out_size;
    const float* v     = (const float*)d_in[0];
    const float* q     = (const float*)d_in[1];
    const float* vmask = (const float*)d_in[2];
    const float* qmask = (const float*)d_in[3];
    const float* Wv    = (const float*)d_in[4];
    const float* bv    = (const float*)d_in[5];
    const float* Wq    = (const float*)d_in[6];
    const float* bq    = (const float*)d_in[7];
    const float* Wvo   = (const float*)d_in[8];
    const float* bvo   = (const float*)d_in[9];
    const float* Wqo   = (const float*)d_in[10];
    const float* bqo   = (const float*)d_in[11];

    float* out_v = (float*)d_out;                         // [8192, 2048]
    float* out_q = out_v + (size_t)ROWS * OS_W;           // [8192, 2048]

    float *vtrans, *qtrans, *vupd, *qupd;
    cudaGetSymbolAddress((void**)&vtrans, g_vtrans);
    cudaGetSymbolAddress((void**)&qtrans, g_qtrans);
    cudaGetSymbolAddress((void**)&vupd,   g_vupd);
    cudaGetSymbolAddress((void**)&qupd,   g_qupd);

    cudaFuncSetAttribute(attn_kernel, cudaFuncAttributeMaxDynamicSharedMemorySize,
                         (int)sizeof(AttnSmem));

    dim3 blk(256);

    // 1) v_trans = relu(v @ Wv + bv) * v_mask     [8192,6144] K=2048
    mma_gemm_kernel<<<dim3(TRANS_W / 128, ROWS / 128), blk>>>(
        v, Wv, vtrans, bv, vmask, ROWS, TRANS_W, 2048, 0, 1);
    // 2) q_trans = relu(q @ Wq + bq) * q_mask     [8192,6144] K=1024
    mma_gemm_kernel<<<dim3(TRANS_W / 128, ROWS / 128), blk>>>(
        q, Wq, qtrans, bq, qmask, ROWS, TRANS_W, 1024, 0, 1);

    // 3) q2v attention: queries=v_trans, keys/vals=q_trans -> v_update
    attn_kernel<<<dim3(8, 16, 16), blk, sizeof(AttnSmem)>>>(vtrans, qtrans, qmask, vupd);
    // 4) v2q attention: queries=q_trans, keys/vals=v_trans -> q_update
    attn_kernel<<<dim3(8, 16, 16), blk, sizeof(AttnSmem)>>>(qtrans, vtrans, vmask, qupd);

    // 5) updated_v = relu([v, v_update] @ Wvo + bvo)   (split-K accumulate)
    mma_gemm_kernel<<<dim3(OS_W / 128, ROWS / 128), blk>>>(
        v, Wvo, out_v, nullptr, nullptr, ROWS, OS_W, 2048, 0, 0);
    mma_gemm_kernel<<<dim3(OS_W / 128, ROWS / 128), blk>>>(
        vupd, Wvo + (size_t)2048 * OS_W, out_v, bvo, nullptr, ROWS, OS_W, 2048, 1, 1);

    // 6) updated_q = relu([q, q_update] @ Wqo + bqo)
    mma_gemm_kernel<<<dim3(OS_W / 128, ROWS / 128), blk>>>(
        q, Wqo, out_q, nullptr, nullptr, ROWS, OS_W, 1024, 0, 0);
    mma_gemm_kernel<<<dim3(OS_W / 128, ROWS / 128), blk>>>(
        qupd, Wqo + (size_t)1024 * OS_W, out_q, bqo, nullptr, ROWS, OS_W, 2048, 1, 1);
}

// round 3
// speedup vs baseline: 2.5741x; 1.0640x over previous
#include <cuda_runtime.h>
#include <math.h>

// Problem constants
// B=16, N=M=512, VS=2048, QS=1024, OS=2048, H=16, DH=128
#define ROWS      8192        // B * 512
#define TRANS_W   6144        // 3 * OS
#define OS_W      2048

// -------------------- scratch (device globals; no allocations allowed) -----
__device__ float g_vtrans[(size_t)ROWS * TRANS_W];
__device__ float g_qtrans[(size_t)ROWS * TRANS_W];
__device__ float g_vupd  [(size_t)ROWS * OS_W];
__device__ float g_qupd  [(size_t)ROWS * OS_W];

// ============================================================================
// TF32 tensor-core GEMM, double-buffered SMEM.
// C[M,N] (+)= A[M,K] @ B[K,N]; epilogue relu(x+bias[col])*mask[row] optional.
// CTA tile 128x128, BK=16, 256 threads = 8 warps (2x4), warp tile 64x32.
// One __syncthreads per K-chunk; LDG prefetch overlaps MMA.
// ============================================================================
#define BM 128
#define BN 128
#define BK 16
#define AS_STRIDE 20
#define BS_STRIDE 136

__device__ __forceinline__ unsigned f2tf32(float x) {
    unsigned r;
    asm("cvt.rna.tf32.f32 %0, %1;" : "=r"(r) : "f"(x));
    return r;
}

__device__ __forceinline__ void mma_tf32(float c[4], const unsigned a[4], const unsigned b[2]) {
    asm volatile(
        "mma.sync.aligned.m16n8k8.row.col.f32.tf32.tf32.f32 "
        "{%0,%1,%2,%3}, {%4,%5,%6,%7}, {%8,%9}, {%0,%1,%2,%3};\n"
        : "+f"(c[0]), "+f"(c[1]), "+f"(c[2]), "+f"(c[3])
        : "r"(a[0]), "r"(a[1]), "r"(a[2]), "r"(a[3]),
          "r"(b[0]), "r"(b[1]));
}

__global__ void __launch_bounds__(256, 2)
mma_gemm_kernel(const float* __restrict__ A, const float* __restrict__ Bm,
                float* __restrict__ C,
                const float* __restrict__ bias, const float* __restrict__ mask,
                int M, int N, int K, int accumulate, int epilogue)
{
    __shared__ unsigned As[2][BM][AS_STRIDE];   // [stage][m][k]
    __shared__ unsigned Bs[2][BK][BS_STRIDE];   // [stage][k][n]

    const int tid  = threadIdx.x;
    const int lane = tid & 31;
    const int warp = tid >> 5;
    const int wm = (warp >> 2) * 64;   // 0 or 64
    const int wn = (warp & 3) * 32;    // 0,32,64,96

    const int rowBase = blockIdx.y * BM;
    const int colBase = blockIdx.x * BN;

    const int aR0 = tid >> 2;              // row 0..63
    const int aK0 = (tid & 3) << 2;        // k offset 0/4/8/12
    const int aR1 = aR0 + 64;              // row 64..127
    const int bR0 = tid >> 5;              // k row 0..7
    const int bC0 = (tid & 31) << 2;       // col 0..124
    const int bR1 = bR0 + 8;               // k row 8..15

    const float* Ap0 = A + (size_t)(rowBase + aR0) * K + aK0;
    const float* Ap1 = A + (size_t)(rowBase + aR1) * K + aK0;
    const float* Bp0 = Bm + (size_t)bR0 * N + colBase + bC0;
    const float* Bp1 = Bm + (size_t)bR1 * N + colBase + bC0;

    float acc[4][4][4];
#pragma unroll
    for (int i = 0; i < 4; i++)
#pragma unroll
        for (int j = 0; j < 4; j++)
#pragma unroll
            for (int r = 0; r < 4; r++) acc[i][j][r] = 0.0f;

    const int kChunks = K / BK;

    // prologue: prefetch chunk 0
    float4 ra0 = *(const float4*)Ap0;
    float4 ra1 = *(const float4*)Ap1;
    float4 rb0 = *(const float4*)Bp0;
    float4 rb1 = *(const float4*)Bp1;

    for (int ck = 0; ck < kChunks; ck++) {
        const int cur = ck & 1;

        // store prefetched chunk -> stage cur (convert to tf32)
        As[cur][aR0][aK0 + 0] = f2tf32(ra0.x);
        As[cur][aR0][aK0 + 1] = f2tf32(ra0.y);
        As[cur][aR0][aK0 + 2] = f2tf32(ra0.z);
        As[cur][aR0][aK0 + 3] = f2tf32(ra0.w);
        As[cur][aR1][aK0 + 0] = f2tf32(ra1.x);
        As[cur][aR1][aK0 + 1] = f2tf32(ra1.y);
        As[cur][aR1][aK0 + 2] = f2tf32(ra1.z);
        As[cur][aR1][aK0 + 3] = f2tf32(ra1.w);
        Bs[cur][bR0][bC0 + 0] = f2tf32(rb0.x);
        Bs[cur][bR0][bC0 + 1] = f2tf32(rb0.y);
        Bs[cur][bR0][bC0 + 2] = f2tf32(rb0.z);
        Bs[cur][bR0][bC0 + 3] = f2tf32(rb0.w);
        Bs[cur][bR1][bC0 + 0] = f2tf32(rb1.x);
        Bs[cur][bR1][bC0 + 1] = f2tf32(rb1.y);
        Bs[cur][bR1][bC0 + 2] = f2tf32(rb1.z);
        Bs[cur][bR1][bC0 + 3] = f2tf32(rb1.w);
        __syncthreads();

        // prefetch next chunk (LDG latency hidden by compute below)
        if (ck + 1 < kChunks) {
            Ap0 += BK; Ap1 += BK;
            Bp0 += (size_t)BK * N; Bp1 += (size_t)BK * N;
            ra0 = *(const float4*)Ap0;
            ra1 = *(const float4*)Ap1;
            rb0 = *(const float4*)Bp0;
            rb1 = *(const float4*)Bp1;
        }

        // compute: two k8 steps from stage cur
#pragma unroll
        for (int ks = 0; ks < 2; ks++) {
            const int k0 = ks * 8;
            unsigned afr[4][4];
#pragma unroll
            for (int mt = 0; mt < 4; mt++) {
                int r = wm + mt * 16 + (lane >> 2);
                int kk = k0 + (lane & 3);
                afr[mt][0] = As[cur][r][kk];
                afr[mt][1] = As[cur][r + 8][kk];
                afr[mt][2] = As[cur][r][kk + 4];
                afr[mt][3] = As[cur][r + 8][kk + 4];
            }
            unsigned bfr[4][2];
#pragma unroll
            for (int nt = 0; nt < 4; nt++) {
                int c = wn + nt * 8 + (lane >> 2);
                int kk = k0 + (lane & 3);
                bfr[nt][0] = Bs[cur][kk][c];
                bfr[nt][1] = Bs[cur][kk + 4][c];
            }
#pragma unroll
            for (int mt = 0; mt < 4; mt++)
#pragma unroll
                for (int nt = 0; nt < 4; nt++)
                    mma_tf32(acc[mt][nt], afr[mt], bfr[nt]);
        }
        // no second sync: next-iter store targets the other stage, and a warp
        // can only reach that store after the next sync releases all warps.
    }

    // ---- epilogue ----
#pragma unroll
    for (int mt = 0; mt < 4; mt++) {
        const int r0 = rowBase + wm + mt * 16 + (lane >> 2);
        const int r1 = r0 + 8;
        const float m0 = mask ? mask[r0] : 1.0f;
        const float m1 = mask ? mask[r1] : 1.0f;
#pragma unroll
        for (int nt = 0; nt < 4; nt++) {
            const int c = colBase + wn + nt * 8 + ((lane & 3) << 1);
            float2 v0, v1;
            v0.x = acc[mt][nt][0]; v0.y = acc[mt][nt][1];
            v1.x = acc[mt][nt][2]; v1.y = acc[mt][nt][3];
            float* p0 = C + (size_t)r0 * N + c;
            float* p1 = C + (size_t)r1 * N + c;
            if (accumulate) {
                float2 o0 = *(const float2*)p0;
                float2 o1 = *(const float2*)p1;
                v0.x += o0.x; v0.y += o0.y;
                v1.x += o1.x; v1.y += o1.y;
            }
            if (epilogue) {
                float b0 = bias[c], b1 = bias[c + 1];
                v0.x = fmaxf(v0.x + b0, 0.0f) * m0;
                v0.y = fmaxf(v0.y + b1, 0.0f) * m0;
                v1.x = fmaxf(v1.x + b0, 0.0f) * m1;
                v1.y = fmaxf(v1.y + b1, 0.0f) * m1;
            }
            *(float2*)p0 = v0;
            *(float2*)p1 = v1;
        }
    }
}

// ============================================================================
// Fused attention (flash-style, fp32) — unchanged (passing).
// ============================================================================
struct AttnSmem {
    float Qs[64][129];
    float Ks[64][129];
    float Vs[64][128];
    float Ss[64][65];
    float Mk[64];
};

__global__ void __launch_bounds__(256)
attn_kernel(const float* __restrict__ Tq, const float* __restrict__ Tk,
            const float* __restrict__ maskK, float* __restrict__ out)
{
    extern __shared__ char smem_raw[];
    AttnSmem& sm = *reinterpret_cast<AttnSmem*>(smem_raw);

    const int b  = blockIdx.z;
    const int h  = blockIdx.y;
    const int qt = blockIdx.x;
    const int tid = threadIdx.x;
    const int sr = tid >> 4;
    const int sc = tid & 15;
    const float SCALE = 0.08838834764831845f;  // 1/sqrt(128)

    const float* qbase = Tq + ((size_t)(b * 512 + qt * 64)) * 6144 + 2048 + h * 128;
#pragma unroll
    for (int c = 0; c < 8; c++) {
        int lin = c * 256 + tid;
        int r = lin >> 5;
        int c4 = (lin & 31) << 2;
        float4 v = *(const float4*)(qbase + (size_t)r * 6144 + c4);
        sm.Qs[r][c4 + 0] = v.x;
        sm.Qs[r][c4 + 1] = v.y;
        sm.Qs[r][c4 + 2] = v.z;
        sm.Qs[r][c4 + 3] = v.w;
    }

    float m_i[4], l_i[4], acc[4][8];
#pragma unroll
    for (int ii = 0; ii < 4; ii++) {
        m_i[ii] = -INFINITY;
        l_i[ii] = 0.0f;
#pragma unroll
        for (int j = 0; j < 8; j++) acc[ii][j] = 0.0f;
    }

    const float* kbase = Tk + (size_t)b * 512 * 6144 + h * 128;
    const float* vbase = kbase + 4096;

    for (int kt = 0; kt < 8; kt++) {
        __syncthreads();
        const float* kp = kbase + (size_t)(kt * 64) * 6144;
        const float* vp = vbase + (size_t)(kt * 64) * 6144;
#pragma unroll
        for (int c = 0; c < 8; c++) {
            int lin = c * 256 + tid;
            int r = lin >> 5;
            int c4 = (lin & 31) << 2;
            float4 kv = *(const float4*)(kp + (size_t)r * 6144 + c4);
            sm.Ks[r][c4 + 0] = kv.x;
            sm.Ks[r][c4 + 1] = kv.y;
            sm.Ks[r][c4 + 2] = kv.z;
            sm.Ks[r][c4 + 3] = kv.w;
            float4 vv = *(const float4*)(vp + (size_t)r * 6144 + c4);
            *(float4*)&sm.Vs[r][c4] = vv;
        }
        if (tid < 64) sm.Mk[tid] = maskK[b * 512 + kt * 64 + tid];
        __syncthreads();

        float s[4][4];
#pragma unroll
        for (int ii = 0; ii < 4; ii++)
#pragma unroll
            for (int jj = 0; jj < 4; jj++) s[ii][jj] = 0.0f;

#pragma unroll 8
        for (int k = 0; k < 128; k++) {
            float q0 = sm.Qs[sr * 4 + 0][k];
            float q1 = sm.Qs[sr * 4 + 1][k];
            float q2 = sm.Qs[sr * 4 + 2][k];
            float q3 = sm.Qs[sr * 4 + 3][k];
#pragma unroll
            for (int jj = 0; jj < 4; jj++) {
                float kv = sm.Ks[sc * 4 + jj][k];
                s[0][jj] += q0 * kv;
                s[1][jj] += q1 * kv;
                s[2][jj] += q2 * kv;
                s[3][jj] += q3 * kv;
            }
        }

        float keep[4];
#pragma unroll
        for (int jj = 0; jj < 4; jj++) keep[jj] = sm.Mk[sc * 4 + jj];
#pragma unroll
        for (int ii = 0; ii < 4; ii++)
#pragma unroll
            for (int jj = 0; jj < 4; jj++)
                s[ii][jj] = (keep[jj] != 0.0f) ? s[ii][jj] * SCALE : -INFINITY;

#pragma unroll
        for (int ii = 0; ii < 4; ii++) {
            float tmax = fmaxf(fmaxf(s[ii][0], s[ii][1]), fmaxf(s[ii][2], s[ii][3]));
            tmax = fmaxf(tmax, __shfl_xor_sync(0xffffffffu, tmax, 1));
            tmax = fmaxf(tmax, __shfl_xor_sync(0xffffffffu, tmax, 2));
            tmax = fmaxf(tmax, __shfl_xor_sync(0xffffffffu, tmax, 4));
            tmax = fmaxf(tmax, __shfl_xor_sync(0xffffffffu, tmax, 8));
            float mnew  = fmaxf(m_i[ii], tmax);
            float msafe = (mnew == -INFINITY) ? 0.0f : mnew;
            float corr  = __expf(m_i[ii] - msafe);
            float lsum = 0.0f;
#pragma unroll
            for (int jj = 0; jj < 4; jj++) {
                float p = __expf(s[ii][jj] - msafe);
                sm.Ss[sr * 4 + ii][sc * 4 + jj] = p;
                lsum += p;
            }
            lsum += __shfl_xor_sync(0xffffffffu, lsum, 1);
            lsum += __shfl_xor_sync(0xffffffffu, lsum, 2);
            lsum += __shfl_xor_sync(0xffffffffu, lsum, 4);
            lsum += __shfl_xor_sync(0xffffffffu, lsum, 8);
            l_i[ii] = l_i[ii] * corr + lsum;
            m_i[ii] = mnew;
#pragma unroll
            for (int j = 0; j < 8; j++) acc[ii][j] *= corr;
        }
        __syncwarp();

#pragma unroll 4
        for (int m = 0; m < 64; m++) {
            float4 v0 = *(const float4*)&sm.Vs[m][sc * 8];
            float4 v1 = *(const float4*)&sm.Vs[m][sc * 8 + 4];
#pragma unroll
            for (int ii = 0; ii < 4; ii++) {
                float p = sm.Ss[sr * 4 + ii][m];
                acc[ii][0] += p * v0.x;
                acc[ii][1] += p * v0.y;
                acc[ii][2] += p * v0.z;
                acc[ii][3] += p * v0.w;
                acc[ii][4] += p * v1.x;
                acc[ii][5] += p * v1.y;
                acc[ii][6] += p * v1.z;
                acc[ii][7] += p * v1.w;
            }
        }
    }

#pragma unroll
    for (int ii = 0; ii < 4; ii++) {
        float inv = (l_i[ii] > 0.0f) ? (1.0f / l_i[ii]) : 0.0f;
        size_t orow = (size_t)(b * 512 + qt * 64 + sr * 4 + ii);
        float* op = out + orow * 2048 + h * 128 + sc * 8;
        float4 o0, o1;
        o0.x = acc[ii][0] * inv; o0.y = acc[ii][1] * inv;
        o0.z = acc[ii][2] * inv; o0.w = acc[ii][3] * inv;
        o1.x = acc[ii][4] * inv; o1.y = acc[ii][5] * inv;
        o1.z = acc[ii][6] * inv; o1.w = acc[ii][7] * inv;
        *(float4*)op       = o0;
        *(float4*)(op + 4) = o1;
    }
}

// ============================================================================
extern "C" void kernel_launch(void* const* d_in, const int* in_sizes, int n_in,
                              void* d_out, int out_size)
{
    (void)in_sizes; (void)n_in; (void)out_size;
    const float* v     = (const float*)d_in[0];
    const float* q     = (const float*)d_in[1];
    const float* vmask = (const float*)d_in[2];
    const float* qmask = (const float*)d_in[3];
    const float* Wv    = (const float*)d_in[4];
    const float* bv    = (const float*)d_in[5];
    const float* Wq    = (const float*)d_in[6];
    const float* bq    = (const float*)d_in[7];
    const float* Wvo   = (const float*)d_in[8];
    const float* bvo   = (const float*)d_in[9];
    const float* Wqo   = (const float*)d_in[10];
    const float* bqo   = (const float*)d_in[11];

    float* out_v = (float*)d_out;                         // [8192, 2048]
    float* out_q = out_v + (size_t)ROWS * OS_W;           // [8192, 2048]

    float *vtrans, *qtrans, *vupd, *qupd;
    cudaGetSymbolAddress((void**)&vtrans, g_vtrans);
    cudaGetSymbolAddress((void**)&qtrans, g_qtrans);
    cudaGetSymbolAddress((void**)&vupd,   g_vupd);
    cudaGetSymbolAddress((void**)&qupd,   g_qupd);

    cudaFuncSetAttribute(attn_kernel, cudaFuncAttributeMaxDynamicSharedMemorySize,
                         (int)sizeof(AttnSmem));

    dim3 blk(256);

    // 1) v_trans = relu(v @ Wv + bv) * v_mask     [8192,6144] K=2048
    mma_gemm_kernel<<<dim3(TRANS_W / 128, ROWS / 128), blk>>>(
        v, Wv, vtrans, bv, vmask, ROWS, TRANS_W, 2048, 0, 1);
    // 2) q_trans = relu(q @ Wq + bq) * q_mask     [8192,6144] K=1024
    mma_gemm_kernel<<<dim3(TRANS_W / 128, ROWS / 128), blk>>>(
        q, Wq, qtrans, bq, qmask, ROWS, TRANS_W, 1024, 0, 1);

    // 3) q2v attention: queries=v_trans, keys/vals=q_trans -> v_update
    attn_kernel<<<dim3(8, 16, 16), blk, sizeof(AttnSmem)>>>(vtrans, qtrans, qmask, vupd);
    // 4) v2q attention: queries=q_trans, keys/vals=v_trans -> q_update
    attn_kernel<<<dim3(8, 16, 16), blk, sizeof(AttnSmem)>>>(qtrans, vtrans, vmask, qupd);

    // 5) updated_v = relu([v, v_update] @ Wvo + bvo)   (split-K accumulate)
    mma_gemm_kernel<<<dim3(OS_W / 128, ROWS / 128), blk>>>(
        v, Wvo, out_v, nullptr, nullptr, ROWS, OS_W, 2048, 0, 0);
    mma_gemm_kernel<<<dim3(OS_W / 128, ROWS / 128), blk>>>(
        vupd, Wvo + (size_t)2048 * OS_W, out_v, bvo, nullptr, ROWS, OS_W, 2048, 1, 1);

    // 6) updated_q = relu([q, q_update] @ Wqo + bqo)
    mma_gemm_kernel<<<dim3(OS_W / 128, ROWS / 128), blk>>>(
        q, Wqo, out_q, nullptr, nullptr, ROWS, OS_W, 1024, 0, 0);
    mma_gemm_kernel<<<dim3(OS_W / 128, ROWS / 128), blk>>>(
        qupd, Wqo + (size_t)1024 * OS_W, out_q, bqo, nullptr, ROWS, OS_W, 2048, 1, 1);
}

// round 4
// speedup vs baseline: 3.5088x; 1.3631x over previous
#include <cuda_runtime.h>
#include <math.h>

// Problem constants
// B=16, N=M=512, VS=2048, QS=1024, OS=2048, H=16, DH=128
#define ROWS      8192        // B * 512
#define TRANS_W   6144        // 3 * OS
#define OS_W      2048

// -------------------- scratch (device globals; no allocations allowed) -----
__device__ float g_vtrans[(size_t)ROWS * TRANS_W];
__device__ float g_qtrans[(size_t)ROWS * TRANS_W];
__device__ float g_vupd  [(size_t)ROWS * OS_W];
__device__ float g_qupd  [(size_t)ROWS * OS_W];

__device__ __forceinline__ unsigned f2tf32(float x) {
    unsigned r;
    asm("cvt.rna.tf32.f32 %0, %1;" : "=r"(r) : "f"(x));
    return r;
}

__device__ __forceinline__ void mma_tf32(float c[4], const unsigned a[4], const unsigned b[2]) {
    asm volatile(
        "mma.sync.aligned.m16n8k8.row.col.f32.tf32.tf32.f32 "
        "{%0,%1,%2,%3}, {%4,%5,%6,%7}, {%8,%9}, {%0,%1,%2,%3};\n"
        : "+f"(c[0]), "+f"(c[1]), "+f"(c[2]), "+f"(c[3])
        : "r"(a[0]), "r"(a[1]), "r"(a[2]), "r"(a[3]),
          "r"(b[0]), "r"(b[1]));
}

// ============================================================================
// TF32 tensor-core GEMM, double-buffered SMEM (unchanged from R3, passing).
// ============================================================================
#define BM 128
#define BN 128
#define BK 16
#define AS_STRIDE 20
#define BS_STRIDE 136

__global__ void __launch_bounds__(256, 2)
mma_gemm_kernel(const float* __restrict__ A, const float* __restrict__ Bm,
                float* __restrict__ C,
                const float* __restrict__ bias, const float* __restrict__ mask,
                int M, int N, int K, int accumulate, int epilogue)
{
    __shared__ unsigned As[2][BM][AS_STRIDE];
    __shared__ unsigned Bs[2][BK][BS_STRIDE];

    const int tid  = threadIdx.x;
    const int lane = tid & 31;
    const int warp = tid >> 5;
    const int wm = (warp >> 2) * 64;
    const int wn = (warp & 3) * 32;

    const int rowBase = blockIdx.y * BM;
    const int colBase = blockIdx.x * BN;

    const int aR0 = tid >> 2;
    const int aK0 = (tid & 3) << 2;
    const int aR1 = aR0 + 64;
    const int bR0 = tid >> 5;
    const int bC0 = (tid & 31) << 2;
    const int bR1 = bR0 + 8;

    const float* Ap0 = A + (size_t)(rowBase + aR0) * K + aK0;
    const float* Ap1 = A + (size_t)(rowBase + aR1) * K + aK0;
    const float* Bp0 = Bm + (size_t)bR0 * N + colBase + bC0;
    const float* Bp1 = Bm + (size_t)bR1 * N + colBase + bC0;

    float acc[4][4][4];
#pragma unroll
    for (int i = 0; i < 4; i++)
#pragma unroll
        for (int j = 0; j < 4; j++)
#pragma unroll
            for (int r = 0; r < 4; r++) acc[i][j][r] = 0.0f;

    const int kChunks = K / BK;

    float4 ra0 = *(const float4*)Ap0;
    float4 ra1 = *(const float4*)Ap1;
    float4 rb0 = *(const float4*)Bp0;
    float4 rb1 = *(const float4*)Bp1;

    for (int ck = 0; ck < kChunks; ck++) {
        const int cur = ck & 1;

        As[cur][aR0][aK0 + 0] = f2tf32(ra0.x);
        As[cur][aR0][aK0 + 1] = f2tf32(ra0.y);
        As[cur][aR0][aK0 + 2] = f2tf32(ra0.z);
        As[cur][aR0][aK0 + 3] = f2tf32(ra0.w);
        As[cur][aR1][aK0 + 0] = f2tf32(ra1.x);
        As[cur][aR1][aK0 + 1] = f2tf32(ra1.y);
        As[cur][aR1][aK0 + 2] = f2tf32(ra1.z);
        As[cur][aR1][aK0 + 3] = f2tf32(ra1.w);
        Bs[cur][bR0][bC0 + 0] = f2tf32(rb0.x);
        Bs[cur][bR0][bC0 + 1] = f2tf32(rb0.y);
        Bs[cur][bR0][bC0 + 2] = f2tf32(rb0.z);
        Bs[cur][bR0][bC0 + 3] = f2tf32(rb0.w);
        Bs[cur][bR1][bC0 + 0] = f2tf32(rb1.x);
        Bs[cur][bR1][bC0 + 1] = f2tf32(rb1.y);
        Bs[cur][bR1][bC0 + 2] = f2tf32(rb1.z);
        Bs[cur][bR1][bC0 + 3] = f2tf32(rb1.w);
        __syncthreads();

        if (ck + 1 < kChunks) {
            Ap0 += BK; Ap1 += BK;
            Bp0 += (size_t)BK * N; Bp1 += (size_t)BK * N;
            ra0 = *(const float4*)Ap0;
            ra1 = *(const float4*)Ap1;
            rb0 = *(const float4*)Bp0;
            rb1 = *(const float4*)Bp1;
        }

#pragma unroll
        for (int ks = 0; ks < 2; ks++) {
            const int k0 = ks * 8;
            unsigned afr[4][4];
#pragma unroll
            for (int mt = 0; mt < 4; mt++) {
                int r = wm + mt * 16 + (lane >> 2);
                int kk = k0 + (lane & 3);
                afr[mt][0] = As[cur][r][kk];
                afr[mt][1] = As[cur][r + 8][kk];
                afr[mt][2] = As[cur][r][kk + 4];
                afr[mt][3] = As[cur][r + 8][kk + 4];
            }
            unsigned bfr[4][2];
#pragma unroll
            for (int nt = 0; nt < 4; nt++) {
                int c = wn + nt * 8 + (lane >> 2);
                int kk = k0 + (lane & 3);
                bfr[nt][0] = Bs[cur][kk][c];
                bfr[nt][1] = Bs[cur][kk + 4][c];
            }
#pragma unroll
            for (int mt = 0; mt < 4; mt++)
#pragma unroll
                for (int nt = 0; nt < 4; nt++)
                    mma_tf32(acc[mt][nt], afr[mt], bfr[nt]);
        }
    }

#pragma unroll
    for (int mt = 0; mt < 4; mt++) {
        const int r0 = rowBase + wm + mt * 16 + (lane >> 2);
        const int r1 = r0 + 8;
        const float m0 = mask ? mask[r0] : 1.0f;
        const float m1 = mask ? mask[r1] : 1.0f;
#pragma unroll
        for (int nt = 0; nt < 4; nt++) {
            const int c = colBase + wn + nt * 8 + ((lane & 3) << 1);
            float2 v0, v1;
            v0.x = acc[mt][nt][0]; v0.y = acc[mt][nt][1];
            v1.x = acc[mt][nt][2]; v1.y = acc[mt][nt][3];
            float* p0 = C + (size_t)r0 * N + c;
            float* p1 = C + (size_t)r1 * N + c;
            if (accumulate) {
                float2 o0 = *(const float2*)p0;
                float2 o1 = *(const float2*)p1;
                v0.x += o0.x; v0.y += o0.y;
                v1.x += o1.x; v1.y += o1.y;
            }
            if (epilogue) {
                float b0 = bias[c], b1 = bias[c + 1];
                v0.x = fmaxf(v0.x + b0, 0.0f) * m0;
                v0.y = fmaxf(v0.y + b1, 0.0f) * m0;
                v1.x = fmaxf(v1.x + b0, 0.0f) * m1;
                v1.y = fmaxf(v1.y + b1, 0.0f) * m1;
            }
            *(float2*)p0 = v0;
            *(float2*)p1 = v1;
        }
    }
}

// ============================================================================
// TF32 tensor-core flash attention.
// Block: 256 threads (8 warps), 128 query rows; each warp owns 16 rows
// exclusively -> softmax state is warp-private. 8 key chunks of 64.
// Fragment addressing verified conflict-free (strides 132/136; P stride 68).
// ============================================================================
struct AttnSmem2 {
    unsigned Qs[128][132];   // tf32 Q tile   [q][d]
    unsigned Ks[64][132];    // tf32 K chunk  [key][d]
    unsigned Vs[64][136];    // tf32 V chunk  [key][d]
    unsigned Ps[128][68];    // tf32 probs    [q][key]
    float    Mk[64];
};

__global__ void __launch_bounds__(256)
attn_mma_kernel(const float* __restrict__ Tq, const float* __restrict__ Tk,
                const float* __restrict__ maskK, float* __restrict__ out)
{
    extern __shared__ char smem_raw[];
    AttnSmem2& sm = *reinterpret_cast<AttnSmem2*>(smem_raw);

    const int b  = blockIdx.z;
    const int h  = blockIdx.y;
    const int qt = blockIdx.x;     // 0..3, 128 rows each
    const int tid  = threadIdx.x;
    const int lane = tid & 31;
    const int warp = tid >> 5;
    const int r0   = warp * 16;    // query rows owned by this warp
    const int gid  = lane >> 2;    // 0..7
    const int tig  = lane & 3;     // 0..3
    const float SCALE = 0.08838834764831845f;  // 1/sqrt(128)

    // ---- load Q tile [128 x 128] -> tf32 smem ----
    const float* qbase = Tq + (size_t)(b * 512 + qt * 128) * 6144 + 2048 + h * 128;
#pragma unroll
    for (int it = 0; it < 16; it++) {
        int lin = it * 256 + tid;
        int r = lin >> 5, c4 = (lin & 31) << 2;
        float4 v = *(const float4*)(qbase + (size_t)r * 6144 + c4);
        uint4 u = { f2tf32(v.x), f2tf32(v.y), f2tf32(v.z), f2tf32(v.w) };
        *(uint4*)&sm.Qs[r][c4] = u;
    }

    float m_i[2] = { -INFINITY, -INFINITY };
    float l_i[2] = { 0.0f, 0.0f };
    float oacc[16][4];
#pragma unroll
    for (int nt = 0; nt < 16; nt++)
#pragma unroll
        for (int j = 0; j < 4; j++) oacc[nt][j] = 0.0f;

    const float* kbase = Tk + (size_t)b * 512 * 6144 + h * 128;   // keys
    const float* vbase = kbase + 4096;                             // vals

    for (int kt = 0; kt < 8; kt++) {
        __syncthreads();   // WAR: prior chunk's MMA reads done before overwrite
#pragma unroll
        for (int it = 0; it < 8; it++) {
            int lin = it * 256 + tid;
            int r = lin >> 5, c4 = (lin & 31) << 2;
            float4 kv = *(const float4*)(kbase + (size_t)(kt * 64 + r) * 6144 + c4);
            uint4 ku = { f2tf32(kv.x), f2tf32(kv.y), f2tf32(kv.z), f2tf32(kv.w) };
            *(uint4*)&sm.Ks[r][c4] = ku;
            float4 vv = *(const float4*)(vbase + (size_t)(kt * 64 + r) * 6144 + c4);
            uint4 vu = { f2tf32(vv.x), f2tf32(vv.y), f2tf32(vv.z), f2tf32(vv.w) };
            *(uint4*)&sm.Vs[r][c4] = vu;
        }
        if (tid < 64) sm.Mk[tid] = maskK[b * 512 + kt * 64 + tid];
        __syncthreads();

        // ---- scores: warp computes S[16 x 64] over d=128 ----
        float c[8][4];
#pragma unroll
        for (int nt = 0; nt < 8; nt++)
#pragma unroll
            for (int j = 0; j < 4; j++) c[nt][j] = 0.0f;

#pragma unroll
        for (int k8 = 0; k8 < 16; k8++) {
            const int kk = k8 * 8 + tig;
            unsigned a[4];
            a[0] = sm.Qs[r0 + gid][kk];
            a[1] = sm.Qs[r0 + gid + 8][kk];
            a[2] = sm.Qs[r0 + gid][kk + 4];
            a[3] = sm.Qs[r0 + gid + 8][kk + 4];
#pragma unroll
            for (int nt = 0; nt < 8; nt++) {
                unsigned bf[2];
                bf[0] = sm.Ks[nt * 8 + gid][kk];
                bf[1] = sm.Ks[nt * 8 + gid][kk + 4];
                mma_tf32(c[nt], a, bf);
            }
        }

        // ---- mask + scale ----
#pragma unroll
        for (int nt = 0; nt < 8; nt++) {
            const int col = nt * 8 + tig * 2;
            const float k0m = sm.Mk[col];
            const float k1m = sm.Mk[col + 1];
            c[nt][0] = (k0m != 0.0f) ? c[nt][0] * SCALE : -INFINITY;
            c[nt][1] = (k1m != 0.0f) ? c[nt][1] * SCALE : -INFINITY;
            c[nt][2] = (k0m != 0.0f) ? c[nt][2] * SCALE : -INFINITY;
            c[nt][3] = (k1m != 0.0f) ? c[nt][3] * SCALE : -INFINITY;
        }

        // ---- online softmax per owned row (j=0: row r0+gid, j=1: +8) ----
#pragma unroll
        for (int j = 0; j < 2; j++) {
            float tmax = -INFINITY;
#pragma unroll
            for (int nt = 0; nt < 8; nt++)
                tmax = fmaxf(tmax, fmaxf(c[nt][j * 2], c[nt][j * 2 + 1]));
            tmax = fmaxf(tmax, __shfl_xor_sync(0xffffffffu, tmax, 1));
            tmax = fmaxf(tmax, __shfl_xor_sync(0xffffffffu, tmax, 2));
            float mnew  = fmaxf(m_i[j], tmax);
            float msafe = (mnew == -INFINITY) ? 0.0f : mnew;
            float corr  = __expf(m_i[j] - msafe);
            float lsum = 0.0f;
            const int row = r0 + gid + j * 8;
#pragma unroll
            for (int nt = 0; nt < 8; nt++) {
                float p0 = __expf(c[nt][j * 2]     - msafe);
                float p1 = __expf(c[nt][j * 2 + 1] - msafe);
                lsum += p0 + p1;
                uint2 pu = { f2tf32(p0), f2tf32(p1) };
                *(uint2*)&sm.Ps[row][nt * 8 + tig * 2] = pu;
            }
            lsum += __shfl_xor_sync(0xffffffffu, lsum, 1);
            lsum += __shfl_xor_sync(0xffffffffu, lsum, 2);
            l_i[j] = l_i[j] * corr + lsum;
            m_i[j] = mnew;
#pragma unroll
            for (int nt = 0; nt < 16; nt++) {
                oacc[nt][j * 2]     *= corr;
                oacc[nt][j * 2 + 1] *= corr;
            }
        }
        __syncwarp();   // Ps rows are warp-private; make stores visible in-warp

        // ---- PV: O[16 x 128] += P[16 x 64] @ V[64 x 128] ----
#pragma unroll
        for (int k8 = 0; k8 < 8; k8++) {
            const int kk = k8 * 8 + tig;
            unsigned a[4];
            a[0] = sm.Ps[r0 + gid][kk];
            a[1] = sm.Ps[r0 + gid + 8][kk];
            a[2] = sm.Ps[r0 + gid][kk + 4];
            a[3] = sm.Ps[r0 + gid + 8][kk + 4];
#pragma unroll
            for (int nt = 0; nt < 16; nt++) {
                unsigned bf[2];
                bf[0] = sm.Vs[k8 * 8 + tig][nt * 8 + gid];
                bf[1] = sm.Vs[k8 * 8 + tig + 4][nt * 8 + gid];
                mma_tf32(oacc[nt], a, bf);
            }
        }
    }

    // ---- write output ----
#pragma unroll
    for (int j = 0; j < 2; j++) {
        const float inv = (l_i[j] > 0.0f) ? (1.0f / l_i[j]) : 0.0f;
        const size_t orow = (size_t)(b * 512 + qt * 128 + r0 + gid + j * 8);
        float* op = out + orow * 2048 + h * 128 + tig * 2;
#pragma unroll
        for (int nt = 0; nt < 16; nt++) {
            float2 o;
            o.x = oacc[nt][j * 2]     * inv;
            o.y = oacc[nt][j * 2 + 1] * inv;
            *(float2*)(op + nt * 8) = o;
        }
    }
}

// ============================================================================
extern "C" void kernel_launch(void* const* d_in, const int* in_sizes, int n_in,
                              void* d_out, int out_size)
{
    (void)in_sizes; (void)n_in; (void)out_size;
    const float* v     = (const float*)d_in[0];
    const float* q     = (const float*)d_in[1];
    const float* vmask = (const float*)d_in[2];
    const float* qmask = (const float*)d_in[3];
    const float* Wv    = (const float*)d_in[4];
    const float* bv    = (const float*)d_in[5];
    const float* Wq    = (const float*)d_in[6];
    const float* bq    = (const float*)d_in[7];
    const float* Wvo   = (const float*)d_in[8];
    const float* bvo   = (const float*)d_in[9];
    const float* Wqo   = (const float*)d_in[10];
    const float* bqo   = (const float*)d_in[11];

    float* out_v = (float*)d_out;                         // [8192, 2048]
    float* out_q = out_v + (size_t)ROWS * OS_W;           // [8192, 2048]

    float *vtrans, *qtrans, *vupd, *qupd;
    cudaGetSymbolAddress((void**)&vtrans, g_vtrans);
    cudaGetSymbolAddress((void**)&qtrans, g_qtrans);
    cudaGetSymbolAddress((void**)&vupd,   g_vupd);
    cudaGetSymbolAddress((void**)&qupd,   g_qupd);

    cudaFuncSetAttribute(attn_mma_kernel, cudaFuncAttributeMaxDynamicSharedMemorySize,
                         (int)sizeof(AttnSmem2));

    dim3 blk(256);

    // 1) v_trans = relu(v @ Wv + bv) * v_mask     [8192,6144] K=2048
    mma_gemm_kernel<<<dim3(TRANS_W / 128, ROWS / 128), blk>>>(
        v, Wv, vtrans, bv, vmask, ROWS, TRANS_W, 2048, 0, 1);
    // 2) q_trans = relu(q @ Wq + bq) * q_mask     [8192,6144] K=1024
    mma_gemm_kernel<<<dim3(TRANS_W / 128, ROWS / 128), blk>>>(
        q, Wq, qtrans, bq, qmask, ROWS, TRANS_W, 1024, 0, 1);

    // 3) q2v attention: queries=v_trans, keys/vals=q_trans -> v_update
    attn_mma_kernel<<<dim3(4, 16, 16), blk, sizeof(AttnSmem2)>>>(vtrans, qtrans, qmask, vupd);
    // 4) v2q attention: queries=q_trans, keys/vals=v_trans -> q_update
    attn_mma_kernel<<<dim3(4, 16, 16), blk, sizeof(AttnSmem2)>>>(qtrans, vtrans, vmask, qupd);

    // 5) updated_v = relu([v, v_update] @ Wvo + bvo)   (split-K accumulate)
    mma_gemm_kernel<<<dim3(OS_W / 128, ROWS / 128), blk>>>(
        v, Wvo, out_v, nullptr, nullptr, ROWS, OS_W, 2048, 0, 0);
    mma_gemm_kernel<<<dim3(OS_W / 128, ROWS / 128), blk>>>(
        vupd, Wvo + (size_t)2048 * OS_W, out_v, bvo, nullptr, ROWS, OS_W, 2048, 1, 1);

    // 6) updated_q = relu([q, q_update] @ Wqo + bqo)
    mma_gemm_kernel<<<dim3(OS_W / 128, ROWS / 128), blk>>>(
        q, Wqo, out_q, nullptr, nullptr, ROWS, OS_W, 1024, 0, 0);
    mma_gemm_kernel<<<dim3(OS_W / 128, ROWS / 128), blk>>>(
        qupd, Wqo + (size_t)1024 * OS_W, out_q, bqo, nullptr, ROWS, OS_W, 2048, 1, 1);
}